// round 14
// baseline (speedup 1.0000x reference)
#include <cuda_runtime.h>
#include <cstdint>

// Gated delta rule: S_t = S_{t-1} @ A_t + B_t.  T=128, 64 chains, D=64.
// R13 = R11 warp-k-split design with ALL memory ops as plain C++ loads/stores
// (barrier-safe AND schedulable; R12 proved volatile-asm serializes, R11 proved
// unannotated asm races). Pure-register asm only for pk2 / f32x2 fma/add.
//
// 128 CTAs (2/chain, 32 rows) x 128 threads (4 warps). Warp w: partial over
// k in [16w,16w+16) for the full 32x64 tile (8x8 per thread).
// Reduction: w1->Pa, w2->Pb, w3->Pc, w0 loads Bm | sync |
//            w0: acc+Pa+Pb+Pc+Bm -> Snext;  w1,w3: stream out S_{t-1}.

#define T_DIM 128
#define BH 64
#define D 64
#define ROWS 32
#define THREADS 128
#define TSTRIDE (BH * D * D)

#define AB0_OFF 0
#define AB1_OFF 16384
#define SB0_OFF 32768
#define SB1_OFF 40960
#define PA_OFF  49152
#define PB_OFF  57344
#define PC_OFF  65536
#define SMEM_BYTES 73728

__device__ __forceinline__ uint32_t smem_u32(const void* p) {
    return (uint32_t)__cvta_generic_to_shared(p);
}
__device__ __forceinline__ unsigned long long pk2(float lo, float hi) {
    unsigned long long r;
    asm("mov.b64 %0,{%1,%2};" : "=l"(r) : "f"(lo), "f"(hi));
    return r;
}
__device__ __forceinline__ unsigned long long f2fma(unsigned long long a,
                                                    unsigned long long b,
                                                    unsigned long long c) {
    unsigned long long d;
    asm("fma.rn.f32x2 %0,%1,%2,%3;" : "=l"(d) : "l"(a), "l"(b), "l"(c));
    return d;
}
__device__ __forceinline__ unsigned long long f2add(unsigned long long a,
                                                    unsigned long long b) {
    unsigned long long d;
    asm("add.rn.f32x2 %0,%1,%2;" : "=l"(d) : "l"(a), "l"(b));
    return d;
}
__device__ __forceinline__ ulonglong2 mk2(unsigned long long x,
                                          unsigned long long y) {
    ulonglong2 r; r.x = x; r.y = y; return r;
}

__global__ void __launch_bounds__(THREADS, 1) gdr_kernel(
    const float* __restrict__ A,
    const float* __restrict__ Bm,
    const float* __restrict__ S0,
    float* __restrict__ out)
{
    extern __shared__ char smem[];
    char* SM = smem;
    const uint32_t SMB = smem_u32(smem);

    const int tid  = threadIdx.x;
    const int lane = tid & 31;
    const int wid  = tid >> 5;
    const int rg   = lane >> 3;      // row group: rows 8rg..8rg+7
    const int cg   = lane & 7;       // col group: cols 8cg..8cg+7
    const int kb   = wid * 16;       // this warp's k range

    const int chain = blockIdx.x >> 1;
    const int half  = blockIdx.x & 1;
    const int r0base = half * ROWS;
    const long chainOff = (long)chain * (D * D);

    const int tileOff = cg * 8 * 128 + rg * 32;   // in [c][r] 8KB buffers

    // ---- prologue: A[0] via cp.async (linear [k][j], 256B per k) ----
    {
        uint32_t s = SMB + AB0_OFF + tid * 16;
        const float* g = A + chainOff + tid * 4;
        #pragma unroll
        for (int i = 0; i < 8; i++) {
            asm volatile("cp.async.cg.shared.global [%0],[%1],16;"
                         :: "r"(s + i * 2048), "l"(g + i * 512));
        }
        asm volatile("cp.async.commit_group;");
    }

    // Init Sb0[k*32 + r] = S0[r][k]
    {
        float* Sb0f = (float*)(SM + SB0_OFF);
        int rl = tid & 31;
        int kk0 = (tid >> 5) * 16;
        const float* g = S0 + chainOff + (long)(r0base + rl) * D + kk0;
        #pragma unroll
        for (int kk = 0; kk < 16; kk++)
            Sb0f[(kk0 + kk) * 32 + rl] = g[kk];
    }

    // ---- main time loop ----
    for (int t = 0; t < T_DIM; t++) {
        asm volatile("cp.async.wait_group 0;" ::: "memory");
        __syncthreads();   // A[t] + S_{t-1} ready; S_t buffer free

        const int cur = t & 1;
        char* Acur  = SM + (cur ? AB1_OFF : AB0_OFF);
        char* Scur  = SM + (cur ? SB1_OFF : SB0_OFF);
        char* Snext = SM + (cur ? SB0_OFF : SB1_OFF);

        // prefetch A[t+1]
        if (t + 1 < T_DIM) {
            uint32_t s = SMB + (cur ? AB0_OFF : AB1_OFF) + tid * 16;
            const float* g = A + (long)(t + 1) * TSTRIDE + chainOff + tid * 4;
            #pragma unroll
            for (int i = 0; i < 8; i++) {
                asm volatile("cp.async.cg.shared.global [%0],[%1],16;"
                             :: "r"(s + i * 2048), "l"(g + i * 512));
            }
            asm volatile("cp.async.commit_group;");
        }

        // accumulators: 4 row-pairs x 8 cols (this warp's k-partial)
        unsigned long long acc[4][8];
        #pragma unroll
        for (int p = 0; p < 4; p++)
            #pragma unroll
            for (int j = 0; j < 8; j++) acc[p][j] = 0ull;

        // ---- k-loop: 16 k's, 8x8 tile, plain C++ loads ----
        {
            const char* sB = Scur + kb * 128 + rg * 32;
            const char* aB = Acur + kb * 256 + cg * 32;
            #pragma unroll
            for (int k2 = 0; k2 < 16; k2++) {
                ulonglong2 sv01 = *(const ulonglong2*)(sB + k2 * 128);
                ulonglong2 sv23 = *(const ulonglong2*)(sB + k2 * 128 + 16);
                float4 a03 = *(const float4*)(aB + k2 * 256);
                float4 a47 = *(const float4*)(aB + k2 * 256 + 16);
                float av[8] = {a03.x, a03.y, a03.z, a03.w,
                               a47.x, a47.y, a47.z, a47.w};
                #pragma unroll
                for (int j = 0; j < 8; j++) {
                    unsigned long long d = pk2(av[j], av[j]);
                    acc[0][j] = f2fma(sv01.x, d, acc[0][j]);
                    acc[1][j] = f2fma(sv01.y, d, acc[1][j]);
                    acc[2][j] = f2fma(sv23.x, d, acc[2][j]);
                    acc[3][j] = f2fma(sv23.y, d, acc[3][j]);
                }
            }
        }

        // ---- phase 1: w1/w2/w3 park partials; w0 loads Bm[t] ----
        float4 bmv[8][2];
        if (wid == 0) {
            const float* g = Bm + (long)t * TSTRIDE + chainOff
                           + (long)(r0base + rg * 8) * D + cg * 8;
            #pragma unroll
            for (int rr = 0; rr < 8; rr++) {
                bmv[rr][0] = *(const float4*)(g + rr * D);
                bmv[rr][1] = *(const float4*)(g + rr * D + 4);
            }
        } else {
            char* p = SM + (wid == 1 ? PA_OFF : wid == 2 ? PB_OFF : PC_OFF)
                    + tileOff;
            #pragma unroll
            for (int j = 0; j < 8; j++) {
                *(ulonglong2*)(p + j * 128)      = mk2(acc[0][j], acc[1][j]);
                *(ulonglong2*)(p + j * 128 + 16) = mk2(acc[2][j], acc[3][j]);
            }
        }
        __syncthreads();

        // ---- phase 2 ----
        if (wid == 0) {
            // final sum: acc + Pa + Pb + Pc + Bm -> Snext
            const char* pa = SM + PA_OFF + tileOff;
            const char* pb = SM + PB_OFF + tileOff;
            const char* pc = SM + PC_OFF + tileOff;
            #pragma unroll
            for (int j = 0; j < 8; j++) {
                ulonglong2 xa0 = *(const ulonglong2*)(pa + j * 128);
                ulonglong2 xa1 = *(const ulonglong2*)(pa + j * 128 + 16);
                ulonglong2 xb0 = *(const ulonglong2*)(pb + j * 128);
                ulonglong2 xb1 = *(const ulonglong2*)(pb + j * 128 + 16);
                ulonglong2 xc0 = *(const ulonglong2*)(pc + j * 128);
                ulonglong2 xc1 = *(const ulonglong2*)(pc + j * 128 + 16);
                acc[0][j] = f2add(f2add(acc[0][j], xa0.x),
                                  f2add(xb0.x, xc0.x));
                acc[1][j] = f2add(f2add(acc[1][j], xa0.y),
                                  f2add(xb0.y, xc0.y));
                acc[2][j] = f2add(f2add(acc[2][j], xa1.x),
                                  f2add(xb1.x, xc1.x));
                acc[3][j] = f2add(f2add(acc[3][j], xa1.y),
                                  f2add(xb1.y, xc1.y));
            }
            // += Bm  (row pairs 2p,2p+1; col j from float4 components)
            #pragma unroll
            for (int p4 = 0; p4 < 4; p4++) {
                const float4 u0 = bmv[2 * p4][0],     u1 = bmv[2 * p4][1];
                const float4 w0 = bmv[2 * p4 + 1][0], w1 = bmv[2 * p4 + 1][1];
                acc[p4][0] = f2add(acc[p4][0], pk2(u0.x, w0.x));
                acc[p4][1] = f2add(acc[p4][1], pk2(u0.y, w0.y));
                acc[p4][2] = f2add(acc[p4][2], pk2(u0.z, w0.z));
                acc[p4][3] = f2add(acc[p4][3], pk2(u0.w, w0.w));
                acc[p4][4] = f2add(acc[p4][4], pk2(u1.x, w1.x));
                acc[p4][5] = f2add(acc[p4][5], pk2(u1.y, w1.y));
                acc[p4][6] = f2add(acc[p4][6], pk2(u1.z, w1.z));
                acc[p4][7] = f2add(acc[p4][7], pk2(u1.w, w1.w));
            }
            char* s = Snext + tileOff;
            #pragma unroll
            for (int j = 0; j < 8; j++) {
                *(ulonglong2*)(s + j * 128)      = mk2(acc[0][j], acc[1][j]);
                *(ulonglong2*)(s + j * 128 + 16) = mk2(acc[2][j], acc[3][j]);
            }
        } else if ((wid == 1 || wid == 3) && t > 0) {
            // stream out S_{t-1} from Scur ([c][r] -> row-major gmem)
            int u = (wid == 1 ? 0 : 32) + lane;   // 0..63
            int r = u >> 1;
            int ch = u & 1;                        // 32-col half
            float v[32];
            #pragma unroll
            for (int j = 0; j < 32; j++)
                v[j] = *(const float*)(Scur + (32 * ch + j) * 128 + r * 4);
            float* o = out + (long)(t - 1) * TSTRIDE + chainOff
                     + (long)(r0base + r) * D + 32 * ch;
            #pragma unroll
            for (int i = 0; i < 8; i++)
                *(float4*)(o + i * 4) = make_float4(v[4*i], v[4*i+1],
                                                    v[4*i+2], v[4*i+3]);
        }
        // next iteration's top __syncthreads publishes Snext and frees P bufs
    }

    // ---- final out-store for t = T-1 (state in Sb0: cur=1 at t=127) ----
    __syncthreads();
    {
        const char* Slast = SM + SB0_OFF;
        int r = tid >> 2;
        int q = tid & 3;                 // 16-col quarter
        float v[16];
        #pragma unroll
        for (int j = 0; j < 16; j++)
            v[j] = *(const float*)(Slast + (16 * q + j) * 128 + r * 4);
        float* o = out + (long)(T_DIM - 1) * TSTRIDE + chainOff
                 + (long)(r0base + r) * D + 16 * q;
        #pragma unroll
        for (int i = 0; i < 4; i++)
            *(float4*)(o + i * 4) = make_float4(v[4*i], v[4*i+1],
                                                v[4*i+2], v[4*i+3]);
    }
}

extern "C" void kernel_launch(void* const* d_in, const int* in_sizes, int n_in,
                              void* d_out, int out_size) {
    const float* A  = (const float*)d_in[0];
    const float* Bm = (const float*)d_in[1];
    const float* S0 = (const float*)d_in[2];
    float* out = (float*)d_out;
    (void)in_sizes; (void)n_in; (void)out_size;

    cudaFuncSetAttribute(gdr_kernel,
                         cudaFuncAttributeMaxDynamicSharedMemorySize,
                         SMEM_BYTES);
    gdr_kernel<<<BH * 2, THREADS, SMEM_BYTES>>>(A, Bm, S0, out);
}

// round 15
// speedup vs baseline: 2.4844x; 2.4844x over previous
#include <cuda_runtime.h>
#include <cstdint>

// Gated delta rule recurrence: S_t = S_{t-1} @ A_t + B_t
// R15 = the 199us R1 kernel + dual k-stream ILP:
//   k split into [0,32) and [32,64), two independent accumulator sets
//   interleaved per iteration (independent LDS/FMA chains), merged at end.
// 128 CTAs (2 per chain, 32 rows) x 128 threads, thread tile 2 rows x 8 cols.
// fp32 via packed fma.rn.f32x2; S smem transposed [k][r]; A double-buffered
// via cp.async; Bm prefetched to registers one step ahead.

#define T_DIM 128
#define BH 64
#define D 64
#define ROWS 32
#define THREADS 128
#define TSTRIDE (BH * D * D)   // 262144 floats per time slice

__device__ __forceinline__ uint32_t smem_u32(const void* p) {
    return (uint32_t)__cvta_generic_to_shared(p);
}
__device__ __forceinline__ unsigned long long pk2(float lo, float hi) {
    unsigned long long r;
    asm("mov.b64 %0,{%1,%2};" : "=l"(r) : "f"(lo), "f"(hi));
    return r;
}
__device__ __forceinline__ void upk2(unsigned long long v, float& lo, float& hi) {
    asm("mov.b64 {%0,%1},%2;" : "=f"(lo), "=f"(hi) : "l"(v));
}
__device__ __forceinline__ unsigned long long f2fma(unsigned long long a,
                                                    unsigned long long b,
                                                    unsigned long long c) {
    unsigned long long d;
    asm("fma.rn.f32x2 %0,%1,%2,%3;" : "=l"(d) : "l"(a), "l"(b), "l"(c));
    return d;
}
__device__ __forceinline__ unsigned long long f2add(unsigned long long a,
                                                    unsigned long long b) {
    unsigned long long d;
    asm("add.rn.f32x2 %0,%1,%2;" : "=l"(d) : "l"(a), "l"(b));
    return d;
}

__global__ void __launch_bounds__(THREADS, 1) gdr_kernel(
    const float* __restrict__ A,
    const float* __restrict__ Bm,
    const float* __restrict__ S0,
    float* __restrict__ out)
{
    __shared__ float Abuf[2][D * D];      // 2 x 16 KB
    __shared__ float Sbuf[2][D * ROWS];   // 2 x 8 KB, transposed: [k][r_local]

    const int tid   = threadIdx.x;
    const int chain = blockIdx.x >> 1;    // 0..63  (b*H + h)
    const int half  = blockIdx.x & 1;     // which 32-row half
    const int r0base = half * ROWS;

    const int rg  = tid & 15;             // row group (2 rows each)
    const int cg  = tid >> 4;             // col group (8 cols each)
    const int j0  = cg * 8;
    const int rl0 = rg * 2;               // local row (even)

    const long chainOff = (long)chain * (D * D);

    // ---------------- prologue ----------------
    {
        uint32_t s = smem_u32(&Abuf[0][0]) + tid * 16;
        const float* g = A + chainOff + tid * 4;
        #pragma unroll
        for (int i = 0; i < 8; i++) {
            asm volatile("cp.async.cg.shared.global [%0],[%1],16;"
                         :: "r"(s + i * 2048), "l"(g + i * 512));
        }
        asm volatile("cp.async.commit_group;");
    }

    // Bm[0] -> registers (2 rows x 8 cols)
    float4 bm00, bm01, bm10, bm11;
    {
        const float* g = Bm + chainOff + (long)(r0base + rl0) * D + j0;
        bm00 = *(const float4*)(g);
        bm01 = *(const float4*)(g + 4);
        bm10 = *(const float4*)(g + D);
        bm11 = *(const float4*)(g + D + 4);
    }

    // Init Sbuf[0] transposed: Sbuf[0][k*ROWS + r] = S0[r][k]
    {
        int rl = tid & 31;
        int kb = (tid >> 5) * 16;
        const float* g = S0 + chainOff + (long)(r0base + rl) * D + kb;
        #pragma unroll
        for (int kk = 0; kk < 16; kk++)
            Sbuf[0][(kb + kk) * ROWS + rl] = g[kk];
    }

    // ---------------- main time loop ----------------
    for (int t = 0; t < T_DIM; t++) {
        asm volatile("cp.async.wait_group 0;" ::: "memory");
        __syncthreads();

        const int cur = t & 1;

        // prefetch A[t+1]
        if (t + 1 < T_DIM) {
            uint32_t s = smem_u32(&Abuf[cur ^ 1][0]) + tid * 16;
            const float* g = A + (long)(t + 1) * TSTRIDE + chainOff + tid * 4;
            #pragma unroll
            for (int i = 0; i < 8; i++) {
                asm volatile("cp.async.cg.shared.global [%0],[%1],16;"
                             :: "r"(s + i * 2048), "l"(g + i * 512));
            }
            asm volatile("cp.async.commit_group;");
        }

        // stream0 acc := Bm[t]; stream1 acc := 0
        unsigned long long a0[4], a1[4], b0[4], b1[4];
        a0[0] = pk2(bm00.x, bm00.y); a0[1] = pk2(bm00.z, bm00.w);
        a0[2] = pk2(bm01.x, bm01.y); a0[3] = pk2(bm01.z, bm01.w);
        a1[0] = pk2(bm10.x, bm10.y); a1[1] = pk2(bm10.z, bm10.w);
        a1[2] = pk2(bm11.x, bm11.y); a1[3] = pk2(bm11.z, bm11.w);
        #pragma unroll
        for (int j = 0; j < 4; j++) { b0[j] = 0ull; b1[j] = 0ull; }

        // prefetch Bm[t+1] (overlaps with the k-loop)
        if (t + 1 < T_DIM) {
            const float* g = Bm + (long)(t + 1) * TSTRIDE + chainOff
                           + (long)(r0base + rl0) * D + j0;
            bm00 = *(const float4*)(g);
            bm01 = *(const float4*)(g + 4);
            bm10 = *(const float4*)(g + D);
            bm11 = *(const float4*)(g + D + 4);
        }

        // k-loop: dual streams (k and k+32), interleaved; acc[r][j] += S[r][k]*A[k][j]
        uint32_t aAddr = smem_u32(&Abuf[cur][0]) + j0 * 4;
        uint32_t sAddr = smem_u32(&Sbuf[cur][0]) + rl0 * 4;
        const uint32_t aOff = 32 * D * 4;      // stream1 A offset (32 k's)
        const uint32_t sOff = 32 * ROWS * 4;   // stream1 S offset

        #pragma unroll
        for (int k = 0; k < 32; k++) {
            // loads, both streams
            unsigned long long xv0, xv1, xv2, xv3, xp;
            unsigned long long yv0, yv1, yv2, yv3, yp;
            asm("ld.shared.v2.b64 {%0,%1},[%2];"
                : "=l"(xv0), "=l"(xv1) : "r"(aAddr));
            asm("ld.shared.v2.b64 {%0,%1},[%2];"
                : "=l"(xv2), "=l"(xv3) : "r"(aAddr + 16));
            asm("ld.shared.b64 %0,[%1];" : "=l"(xp) : "r"(sAddr));
            asm("ld.shared.v2.b64 {%0,%1},[%2];"
                : "=l"(yv0), "=l"(yv1) : "r"(aAddr + aOff));
            asm("ld.shared.v2.b64 {%0,%1},[%2];"
                : "=l"(yv2), "=l"(yv3) : "r"(aAddr + aOff + 16));
            asm("ld.shared.b64 %0,[%1];" : "=l"(yp) : "r"(sAddr + sOff));

            // stream0 math
            float xs0f, xs1f;
            upk2(xp, xs0f, xs1f);
            unsigned long long xs0 = pk2(xs0f, xs0f);
            unsigned long long xs1 = pk2(xs1f, xs1f);
            a0[0] = f2fma(xs0, xv0, a0[0]);
            a0[1] = f2fma(xs0, xv1, a0[1]);
            a0[2] = f2fma(xs0, xv2, a0[2]);
            a0[3] = f2fma(xs0, xv3, a0[3]);
            a1[0] = f2fma(xs1, xv0, a1[0]);
            a1[1] = f2fma(xs1, xv1, a1[1]);
            a1[2] = f2fma(xs1, xv2, a1[2]);
            a1[3] = f2fma(xs1, xv3, a1[3]);

            // stream1 math
            float ys0f, ys1f;
            upk2(yp, ys0f, ys1f);
            unsigned long long ys0 = pk2(ys0f, ys0f);
            unsigned long long ys1 = pk2(ys1f, ys1f);
            b0[0] = f2fma(ys0, yv0, b0[0]);
            b0[1] = f2fma(ys0, yv1, b0[1]);
            b0[2] = f2fma(ys0, yv2, b0[2]);
            b0[3] = f2fma(ys0, yv3, b0[3]);
            b1[0] = f2fma(ys1, yv0, b1[0]);
            b1[1] = f2fma(ys1, yv1, b1[1]);
            b1[2] = f2fma(ys1, yv2, b1[2]);
            b1[3] = f2fma(ys1, yv3, b1[3]);

            aAddr += D * 4;
            sAddr += ROWS * 4;
        }

        // merge streams
        a0[0] = f2add(a0[0], b0[0]); a0[1] = f2add(a0[1], b0[1]);
        a0[2] = f2add(a0[2], b0[2]); a0[3] = f2add(a0[3], b0[3]);
        a1[0] = f2add(a1[0], b1[0]); a1[1] = f2add(a1[1], b1[1]);
        a1[2] = f2add(a1[2], b1[2]); a1[3] = f2add(a1[3], b1[3]);

        // Epilogue: unpack, store to gmem, write Snew transposed to next Sbuf.
        float r0f[8], r1f[8];
        upk2(a0[0], r0f[0], r0f[1]); upk2(a0[1], r0f[2], r0f[3]);
        upk2(a0[2], r0f[4], r0f[5]); upk2(a0[3], r0f[6], r0f[7]);
        upk2(a1[0], r1f[0], r1f[1]); upk2(a1[1], r1f[2], r1f[3]);
        upk2(a1[2], r1f[4], r1f[5]); upk2(a1[3], r1f[6], r1f[7]);

        float* o = out + (long)t * TSTRIDE + chainOff
                 + (long)(r0base + rl0) * D + j0;
        *(float4*)(o)         = make_float4(r0f[0], r0f[1], r0f[2], r0f[3]);
        *(float4*)(o + 4)     = make_float4(r0f[4], r0f[5], r0f[6], r0f[7]);
        *(float4*)(o + D)     = make_float4(r1f[0], r1f[1], r1f[2], r1f[3]);
        *(float4*)(o + D + 4) = make_float4(r1f[4], r1f[5], r1f[6], r1f[7]);

        float* sb = &Sbuf[cur ^ 1][0];
        #pragma unroll
        for (int jj = 0; jj < 8; jj++) {
            *(unsigned long long*)&sb[(j0 + jj) * ROWS + rl0] =
                pk2(r0f[jj], r1f[jj]);
        }
        // next iteration's __syncthreads publishes Sbuf[cur^1]
    }
}

extern "C" void kernel_launch(void* const* d_in, const int* in_sizes, int n_in,
                              void* d_out, int out_size) {
    const float* A  = (const float*)d_in[0];
    const float* Bm = (const float*)d_in[1];
    const float* S0 = (const float*)d_in[2];
    float* out = (float*)d_out;
    (void)in_sizes; (void)n_in; (void)out_size;

    gdr_kernel<<<BH * 2, THREADS>>>(A, Bm, S0, out);
}

// round 16
// speedup vs baseline: 2.5107x; 1.0106x over previous
#include <cuda_runtime.h>
#include <cstdint>

// Gated delta rule: S_t = S_{t-1} @ A_t + B_t.  T=128, 64 chains, D=64.
// R16: row-major S with k-batched LDS -> 2 LDS per k (was 3) + direct out-store.
// 128 CTAs (2/chain, 32 rows) x 128 threads. Thread tile 4 rows x 4 cols,
// rows STRIDED {rg, rg+8, rg+16, rg+24} so the 68-float row pitch gives
// conflict-free banks (4*rg). S smem [r][k] pitch 68; A smem [k][j] 256B.
// Per 4-k block: 4x LDS.128 S (S[r][k..k+3]) + 4x LDS.128 A. One sync/step.

#define T_DIM 128
#define BH 64
#define D 64
#define ROWS 32
#define THREADS 128
#define TSTRIDE (BH * D * D)

#define SPITCH 68                         // floats per S row (64 + 4 pad)
#define AB_BYTES 16384                    // A: [k][j] 64x64 f32
#define SB_BYTES (ROWS * SPITCH * 4)      // 8704
#define AB0_OFF 0
#define AB1_OFF AB_BYTES
#define SB0_OFF (2 * AB_BYTES)
#define SB1_OFF (2 * AB_BYTES + SB_BYTES)
#define SMEM_BYTES (2 * AB_BYTES + 2 * SB_BYTES)   // 50176

__device__ __forceinline__ uint32_t smem_u32(const void* p) {
    return (uint32_t)__cvta_generic_to_shared(p);
}
__device__ __forceinline__ unsigned long long pk2(float lo, float hi) {
    unsigned long long r;
    asm("mov.b64 %0,{%1,%2};" : "=l"(r) : "f"(lo), "f"(hi));
    return r;
}
__device__ __forceinline__ void upk2(unsigned long long v, float& lo, float& hi) {
    asm("mov.b64 {%0,%1},%2;" : "=f"(lo), "=f"(hi) : "l"(v));
}
__device__ __forceinline__ unsigned long long f2fma(unsigned long long a,
                                                    unsigned long long b,
                                                    unsigned long long c) {
    unsigned long long d;
    asm("fma.rn.f32x2 %0,%1,%2,%3;" : "=l"(d) : "l"(a), "l"(b), "l"(c));
    return d;
}

__global__ void __launch_bounds__(THREADS, 1) gdr_kernel(
    const float* __restrict__ A,
    const float* __restrict__ Bm,
    const float* __restrict__ S0,
    float* __restrict__ out)
{
    extern __shared__ char smem[];
    char* SM = smem;
    const uint32_t SMB = smem_u32(smem);

    const int tid  = threadIdx.x;
    const int lane = tid & 31;
    const int w    = tid >> 5;
    const int rg   = lane & 7;            // base row; thread rows rg+8i
    const int cg   = lane >> 3;           // 0..3
    const int c0   = w * 16 + cg * 4;     // col base

    const int chain = blockIdx.x >> 1;
    const int half  = blockIdx.x & 1;
    const int r0base = half * ROWS;
    const long chainOff = (long)chain * (D * D);

    // ---- prologue: A[0] via cp.async (linear [k][j], 256B per k) ----
    {
        uint32_t s = SMB + AB0_OFF + tid * 16;
        const float* g = A + chainOff + tid * 4;
        #pragma unroll
        for (int i = 0; i < 8; i++) {
            asm volatile("cp.async.cg.shared.global [%0],[%1],16;"
                         :: "r"(s + i * 2048), "l"(g + i * 512));
        }
        asm volatile("cp.async.commit_group;");
    }

    // Bm[0] -> registers: rows rg+8i, cols c0..c0+3
    float4 bmv[4];
    {
        const float* g = Bm + chainOff + (long)(r0base + rg) * D + c0;
        #pragma unroll
        for (int i = 0; i < 4; i++)
            bmv[i] = *(const float4*)(g + i * 8 * D);
    }

    // Init Sb0[r][k] = S0[r][k]  (row-major, pitch SPITCH)
    {
        float* Sb0f = (float*)(SM + SB0_OFF);
        int rl = tid & 31;
        int kc = (tid >> 5) * 16;
        const float* g = S0 + chainOff + (long)(r0base + rl) * D + kc;
        float* d = Sb0f + rl * SPITCH + kc;
        #pragma unroll
        for (int i = 0; i < 4; i++)
            *(float4*)(d + i * 4) = *(const float4*)(g + i * 4);
    }

    // ---- main time loop ----
    for (int t = 0; t < T_DIM; t++) {
        asm volatile("cp.async.wait_group 0;" ::: "memory");
        __syncthreads();   // A[t] + S_{t-1} ready; S_t buffer free

        const int cur = t & 1;
        const char* Acur = SM + (cur ? AB1_OFF : AB0_OFF);
        const char* Scur = SM + (cur ? SB1_OFF : SB0_OFF);
        char* Snext      = SM + (cur ? SB0_OFF : SB1_OFF);

        // prefetch A[t+1]
        if (t + 1 < T_DIM) {
            uint32_t s = SMB + (cur ? AB0_OFF : AB1_OFF) + tid * 16;
            const float* g = A + (long)(t + 1) * TSTRIDE + chainOff + tid * 4;
            #pragma unroll
            for (int i = 0; i < 8; i++) {
                asm volatile("cp.async.cg.shared.global [%0],[%1],16;"
                             :: "r"(s + i * 2048), "l"(g + i * 512));
            }
            asm volatile("cp.async.commit_group;");
        }

        // acc[i][p] = (row rg+8i, cols c0+2p, c0+2p+1), init from Bm[t]
        unsigned long long acc[4][2];
        #pragma unroll
        for (int i = 0; i < 4; i++) {
            acc[i][0] = pk2(bmv[i].x, bmv[i].y);
            acc[i][1] = pk2(bmv[i].z, bmv[i].w);
        }

        // prefetch Bm[t+1] (overlaps k-loop)
        if (t + 1 < T_DIM) {
            const float* g = Bm + (long)(t + 1) * TSTRIDE + chainOff
                           + (long)(r0base + rg) * D + c0;
            #pragma unroll
            for (int i = 0; i < 4; i++)
                bmv[i] = *(const float4*)(g + i * 8 * D);
        }

        // ---- k-loop: 16 blocks of 4 k; 8 LDS.128 per block ----
        const char* sB = Scur + rg * (SPITCH * 4);
        const char* aB = Acur + c0 * 4;

        #pragma unroll
        for (int kb = 0; kb < 16; kb++) {
            // S: 4 rows x 4 k's
            float4 sv0 = *(const float4*)(sB + 0 * (8 * SPITCH * 4) + kb * 16);
            float4 sv1 = *(const float4*)(sB + 1 * (8 * SPITCH * 4) + kb * 16);
            float4 sv2 = *(const float4*)(sB + 2 * (8 * SPITCH * 4) + kb * 16);
            float4 sv3 = *(const float4*)(sB + 3 * (8 * SPITCH * 4) + kb * 16);
            // A: 4 k's x 4 cols (as packed pairs)
            ulonglong2 av0 = *(const ulonglong2*)(aB + (kb * 4 + 0) * 256);
            ulonglong2 av1 = *(const ulonglong2*)(aB + (kb * 4 + 1) * 256);
            ulonglong2 av2 = *(const ulonglong2*)(aB + (kb * 4 + 2) * 256);
            ulonglong2 av3 = *(const ulonglong2*)(aB + (kb * 4 + 3) * 256);

            #define STEPK(comp, av) do { \
                unsigned long long d0 = pk2(sv0.comp, sv0.comp); \
                unsigned long long d1 = pk2(sv1.comp, sv1.comp); \
                unsigned long long d2 = pk2(sv2.comp, sv2.comp); \
                unsigned long long d3 = pk2(sv3.comp, sv3.comp); \
                acc[0][0] = f2fma(d0, (av).x, acc[0][0]); \
                acc[0][1] = f2fma(d0, (av).y, acc[0][1]); \
                acc[1][0] = f2fma(d1, (av).x, acc[1][0]); \
                acc[1][1] = f2fma(d1, (av).y, acc[1][1]); \
                acc[2][0] = f2fma(d2, (av).x, acc[2][0]); \
                acc[2][1] = f2fma(d2, (av).y, acc[2][1]); \
                acc[3][0] = f2fma(d3, (av).x, acc[3][0]); \
                acc[3][1] = f2fma(d3, (av).y, acc[3][1]); \
            } while (0)

            STEPK(x, av0);
            STEPK(y, av1);
            STEPK(z, av2);
            STEPK(w, av3);
            #undef STEPK
        }

        // ---- epilogue: direct out-store + Snew row-major ----
        float* o = out + (long)t * TSTRIDE + chainOff
                 + (long)(r0base + rg) * D + c0;
        #pragma unroll
        for (int i = 0; i < 4; i++) {
            float v0, v1, v2, v3;
            upk2(acc[i][0], v0, v1);
            upk2(acc[i][1], v2, v3);
            *(float4*)(o + i * 8 * D) = make_float4(v0, v1, v2, v3);
            *(ulonglong2*)(Snext + (rg + 8 * i) * (SPITCH * 4) + c0 * 4) =
                *(ulonglong2*)&acc[i][0];
        }
        // next iteration's __syncthreads publishes Snext
    }
}

extern "C" void kernel_launch(void* const* d_in, const int* in_sizes, int n_in,
                              void* d_out, int out_size) {
    const float* A  = (const float*)d_in[0];
    const float* Bm = (const float*)d_in[1];
    const float* S0 = (const float*)d_in[2];
    float* out = (float*)d_out;
    (void)in_sizes; (void)n_in; (void)out_size;

    cudaFuncSetAttribute(gdr_kernel,
                         cudaFuncAttributeMaxDynamicSharedMemorySize,
                         SMEM_BYTES);
    gdr_kernel<<<BH * 2, THREADS, SMEM_BYTES>>>(A, Bm, S0, out);
}